// round 13
// baseline (speedup 1.0000x reference)
#include <cuda_runtime.h>
#include <cuda_bf16.h>
#include <math.h>
#include <stdint.h>

#define BATCH 4
#define NTOK  4096
#define DIM   1024
#define NHEAD 16
#define DH    64
#define WS    128
#define NWIN  32
#define QKVN  3072
#define MTOT  (BATCH * NTOK)   // 16384

// ---------------------------------------------------------------------------
// Scratch (static device globals: allocation-free, graph-capturable)
// ---------------------------------------------------------------------------
__device__ float         g_qkv [(size_t)MTOT * QKVN];      // f32 q|k|v
__device__ __nv_bfloat16 g_xh  [(size_t)MTOT * DIM];
__device__ __nv_bfloat16 g_xl  [(size_t)MTOT * DIM];
__device__ __nv_bfloat16 g_wqh [(size_t)QKVN * DIM];
__device__ __nv_bfloat16 g_wql [(size_t)QKVN * DIM];
__device__ __nv_bfloat16 g_woh [(size_t)DIM * DIM];
__device__ __nv_bfloat16 g_wol [(size_t)DIM * DIM];
__device__ __nv_bfloat16 g_ah  [(size_t)MTOT * DIM];
__device__ __nv_bfloat16 g_al  [(size_t)MTOT * DIM];
__device__ float2        g_rope[256 * 32];                 // (sin, cos) per (pos, d)

// ---------------------------------------------------------------------------
// Base-target primitives (compute_103 rejects tcgen05; mma.sync is legal)
// ---------------------------------------------------------------------------
__device__ __forceinline__ uint32_t smem_u32(const void* p) {
    return (uint32_t)__cvta_generic_to_shared(p);
}
__device__ __forceinline__ void cp_async16(uint32_t saddr, const void* gaddr) {
    asm volatile("cp.async.cg.shared.global [%0], [%1], 16;" :: "r"(saddr), "l"(gaddr));
}
#define CP_COMMIT()  asm volatile("cp.async.commit_group;" ::: "memory")
#define CP_WAIT(N)   asm volatile("cp.async.wait_group %0;" :: "n"(N) : "memory")

__device__ __forceinline__ void ldm_x4(uint32_t* r, uint32_t addr) {
    asm volatile("ldmatrix.sync.aligned.m8n8.x4.shared.b16 {%0,%1,%2,%3}, [%4];"
                 : "=r"(r[0]), "=r"(r[1]), "=r"(r[2]), "=r"(r[3]) : "r"(addr));
}
__device__ __forceinline__ void mma16816(float* c, const uint32_t* a, const uint32_t* b) {
    asm volatile("mma.sync.aligned.m16n8k16.row.col.f32.bf16.bf16.f32 "
                 "{%0,%1,%2,%3}, {%4,%5,%6,%7}, {%8,%9}, {%0,%1,%2,%3};"
                 : "+f"(c[0]), "+f"(c[1]), "+f"(c[2]), "+f"(c[3])
                 : "r"(a[0]), "r"(a[1]), "r"(a[2]), "r"(a[3]), "r"(b[0]), "r"(b[1]));
}
__device__ __forceinline__ uint32_t pack_bf16x2(float a, float b) {
    __nv_bfloat162 h = __floats2bfloat162_rn(a, b);
    uint32_t u; *(__nv_bfloat162*)&u = h;
    return u;
}

// ---------------------------------------------------------------------------
// Prep kernels
// ---------------------------------------------------------------------------
__global__ __launch_bounds__(256) void rope_table_kernel()
{
    int idx = blockIdx.x * 256 + threadIdx.x;
    if (idx >= 256 * 32) return;
    int j = idx >> 5, d = idx & 31;
    float inv_freq = expf(-logf(10000.0f) * (float)d * (1.0f / 32.0f));
    float s, c;
    sincosf((float)j * inv_freq, &s, &c);
    g_rope[idx] = make_float2(s, c);
}

__global__ __launch_bounds__(256) void split_f32(const float* __restrict__ src,
                                                 __nv_bfloat16* __restrict__ hi,
                                                 __nv_bfloat16* __restrict__ lo, int n4)
{
    int i = blockIdx.x * 256 + threadIdx.x;
    if (i >= n4) return;
    float4 v = ((const float4*)src)[i];
    float a[4] = {v.x, v.y, v.z, v.w};
#pragma unroll
    for (int j = 0; j < 4; j++) {
        __nv_bfloat16 h = __float2bfloat16(a[j]);
        hi[i * 4 + j] = h;
        lo[i * 4 + j] = __float2bfloat16(a[j] - __bfloat162float(h));
    }
}

__global__ __launch_bounds__(256) void transpose_split(const float* __restrict__ W,
                                                       __nv_bfloat16* __restrict__ Th,
                                                       __nv_bfloat16* __restrict__ Tl,
                                                       int K, int N)
{
    __shared__ float t[32][33];
    int n0 = blockIdx.x * 32, k0 = blockIdx.y * 32;
    int tx = threadIdx.x & 31, ty8 = threadIdx.x >> 5;
#pragma unroll
    for (int r = 0; r < 4; r++) {
        int ky = ty8 + r * 8;
        t[ky][tx] = W[(size_t)(k0 + ky) * N + n0 + tx];
    }
    __syncthreads();
#pragma unroll
    for (int r = 0; r < 4; r++) {
        int ny = ty8 + r * 8;
        float v = t[tx][ny];
        __nv_bfloat16 h = __float2bfloat16(v);
        Th[(size_t)(n0 + ny) * K + k0 + tx] = h;
        Tl[(size_t)(n0 + ny) * K + k0 + tx] = __float2bfloat16(v - __bfloat162float(h));
    }
}

// ---------------------------------------------------------------------------
// bf16x3 GEMM: 128x128 CTA tile, 128 threads / 4 warps, EACH WARP 64x64
// (doubles A/B fragment reuse -> halves ldmatrix/smem-crossbar traffic).
// KC=32, XOR-swizzled 64B rows, 3-stage cp.async, ONE barrier/chunk, 2 CTAs/SM.
// ---------------------------------------------------------------------------
#define KC       32
#define ARR_B    8192
#define STAGE_B  (4 * ARR_B)           // 32768
#define GSMEM_BYTES (3 * STAGE_B)      // 98304

__device__ __forceinline__ uint32_t sw_off(int row, int c16) {
    return (uint32_t)(((row >> 1) << 7) + ((row & 1) << 6)
                      + (((c16 ^ (row >> 1)) & 3) << 4));
}

__global__ __launch_bounds__(128, 2) void gemm_bf16x3(
    const __nv_bfloat16* __restrict__ Ah, const __nv_bfloat16* __restrict__ Al,
    const __nv_bfloat16* __restrict__ Bh, const __nv_bfloat16* __restrict__ Bl,
    float* __restrict__ C, int M, int N, int K)
{
    extern __shared__ char sm[];
    const uint32_t sbase = smem_u32(sm);
    const int tid  = threadIdx.x;
    const int wid  = tid >> 5;           // 0..3
    const int lane = tid & 31;
    const int wr   = (wid >> 1) * 64;    // 0 / 64
    const int wc   = (wid & 1) * 64;     // 0 / 64

    const int r0 = blockIdx.y * 128;
    const int c0 = blockIdx.x * 128;

    const __nv_bfloat16* gsrc[4] = {
        Ah + (size_t)r0 * K, Al + (size_t)r0 * K,
        Bh + (size_t)c0 * K, Bl + (size_t)c0 * K };

    const int ldrow = tid >> 2;          // 0..31
    const int ldseg = tid & 3;           // 0..3

    auto issue = [&](int kc, int s) {
        const uint32_t stb = sbase + s * STAGE_B;
#pragma unroll
        for (int t = 0; t < 4; t++) {
#pragma unroll
            for (int q = 0; q < 4; q++) {
                int row = ldrow + q * 32;
                const void* g = gsrc[t] + (size_t)row * K + kc * KC + ldseg * 8;
                cp_async16(stb + t * ARR_B + sw_off(row, ldseg), g);
            }
        }
    };

    float acc[4][8][4];
#pragma unroll
    for (int mt = 0; mt < 4; mt++)
#pragma unroll
        for (int nt = 0; nt < 8; nt++)
#pragma unroll
            for (int i = 0; i < 4; i++) acc[mt][nt][i] = 0.f;

    const int rl = lane & 15, chh = lane >> 4;
    const uint32_t ltb = (uint32_t)(((rl >> 1) << 7) + ((rl & 1) << 6));
    const uint32_t lt0 = ltb + ((((chh)     ^ (rl >> 1)) & 3) << 4);
    const uint32_t lt1 = ltb + ((((2 + chh) ^ (rl >> 1)) & 3) << 4);

    const int nchunk = K / KC;
    issue(0, 0); CP_COMMIT();
    issue(1, 1); CP_COMMIT();

    int buf = 0;
    for (int kc = 0; kc < nchunk; kc++) {
        if (kc + 1 < nchunk) CP_WAIT(1); else CP_WAIT(0);
        __syncthreads();
        if (kc + 2 < nchunk) {
            int nb = buf + 2; if (nb >= 3) nb -= 3;
            issue(kc + 2, nb);
            CP_COMMIT();
        }

        const uint32_t stb = sbase + buf * STAGE_B;
#pragma unroll
        for (int ks = 0; ks < 2; ks++) {
            const uint32_t lt = ks ? lt1 : lt0;
            uint32_t ah[4][4], al_[4][4];
#pragma unroll
            for (int mt = 0; mt < 4; mt++) {
                uint32_t ra = (uint32_t)(wr + mt * 16) * 64 + lt;
                ldm_x4(ah[mt],  stb + 0 * ARR_B + ra);
                ldm_x4(al_[mt], stb + 1 * ARR_B + ra);
            }
            uint32_t bh[8][2], bl[8][2];
#pragma unroll
            for (int nh = 0; nh < 4; nh++) {
                uint32_t rb = (uint32_t)(wc + nh * 16) * 64 + lt;
                uint32_t r[4];
                ldm_x4(r, stb + 2 * ARR_B + rb);
                bh[nh * 2][0] = r[0]; bh[nh * 2][1] = r[2];
                bh[nh * 2 + 1][0] = r[1]; bh[nh * 2 + 1][1] = r[3];
                ldm_x4(r, stb + 3 * ARR_B + rb);
                bl[nh * 2][0] = r[0]; bl[nh * 2][1] = r[2];
                bl[nh * 2 + 1][0] = r[1]; bl[nh * 2 + 1][1] = r[3];
            }
#pragma unroll
            for (int mt = 0; mt < 4; mt++)
#pragma unroll
                for (int nt = 0; nt < 8; nt++) {
                    mma16816(acc[mt][nt], ah[mt],  bh[nt]);
                    mma16816(acc[mt][nt], ah[mt],  bl[nt]);
                    mma16816(acc[mt][nt], al_[mt], bh[nt]);
                }
        }
        if (++buf == 3) buf = 0;
    }

    const int gr = lane >> 2;
    const int gc = (lane & 3) * 2;
#pragma unroll
    for (int mt = 0; mt < 4; mt++) {
        int row = r0 + wr + mt * 16 + gr;
#pragma unroll
        for (int nt = 0; nt < 8; nt++) {
            int col = c0 + wc + nt * 8 + gc;
            *(float2*)&C[(size_t)row * N + col] =
                make_float2(acc[mt][nt][0], acc[mt][nt][1]);
            *(float2*)&C[(size_t)(row + 8) * N + col] =
                make_float2(acc[mt][nt][2], acc[mt][nt][3]);
        }
    }
}

// ---------------------------------------------------------------------------
// Tensor-core local attention, mask-aware, P in registers (round-11 config).
// ---------------------------------------------------------------------------
#define QK_ROWB 144
#define PV_ROWB 528
#define OFF_QH  0
#define OFF_QL  18432
#define OFF_KH  36864
#define OFF_KL  73728
#define OFF_VH  110592
#define OFF_VL  144384
#define ASMEM_BYTES 178176

__global__ __launch_bounds__(256) void attn_mma_kernel()
{
    extern __shared__ char sm[];
    const uint32_t sb = smem_u32(sm);

    const int widx = blockIdx.x;
    const int h    = blockIdx.y;
    const int bi   = blockIdx.z;
    const int tid  = threadIdx.x;
    const int wid  = tid >> 5;
    const int lane = tid & 31;
    const int d    = tid & 31;
    const int grp  = tid >> 5;

    const float scale = 0.125f;

    const float* qbase = g_qkv + (size_t)(bi * NTOK + widx * WS) * QKVN + h * DH;
#pragma unroll 4
    for (int it = 0; it < 16; it++) {
        int i = grp + 8 * it;
        const float* p = qbase + (size_t)i * QKVN;
        float x1 = p[d], x2 = p[d + 32];
        float2 sc = g_rope[(WS + i) * 32 + d];
        float v1 = (x1 * sc.y - x2 * sc.x) * scale;
        float v2 = (x2 * sc.y + x1 * sc.x) * scale;
        uint32_t row = i * QK_ROWB;
        __nv_bfloat16 b1 = __float2bfloat16(v1), b2 = __float2bfloat16(v2);
        *(__nv_bfloat16*)(sm + OFF_QH + row + d * 2)        = b1;
        *(__nv_bfloat16*)(sm + OFF_QH + row + (d + 32) * 2) = b2;
        *(__nv_bfloat16*)(sm + OFF_QL + row + d * 2)        = __float2bfloat16(v1 - __bfloat162float(b1));
        *(__nv_bfloat16*)(sm + OFF_QL + row + (d + 32) * 2) = __float2bfloat16(v2 - __bfloat162float(b2));
    }
    const float* kbase = g_qkv + (size_t)(bi * NTOK) * QKVN + DIM + h * DH;
#pragma unroll 4
    for (int it = 0; it < 32; it++) {
        int jj  = grp + 8 * it;
        int tok = (widx - 1) * WS + jj;
        float x1 = 0.f, x2 = 0.f;
        if (tok >= 0) {
            const float* p = kbase + (size_t)tok * QKVN;
            x1 = p[d]; x2 = p[d + 32];
        }
        float2 sc = g_rope[jj * 32 + d];
        float v1 = x1 * sc.y - x2 * sc.x;
        float v2 = x2 * sc.y + x1 * sc.x;
        uint32_t row = jj * QK_ROWB;
        __nv_bfloat16 b1 = __float2bfloat16(v1), b2 = __float2bfloat16(v2);
        *(__nv_bfloat16*)(sm + OFF_KH + row + d * 2)        = b1;
        *(__nv_bfloat16*)(sm + OFF_KH + row + (d + 32) * 2) = b2;
        *(__nv_bfloat16*)(sm + OFF_KL + row + d * 2)        = __float2bfloat16(v1 - __bfloat162float(b1));
        *(__nv_bfloat16*)(sm + OFF_KL + row + (d + 32) * 2) = __float2bfloat16(v2 - __bfloat162float(b2));
    }
    const float* vbase = g_qkv + (size_t)(bi * NTOK) * QKVN + 2 * DIM + h * DH;
    for (int idx = tid; idx < 256 * 64; idx += 256) {
        int jj = idx >> 6, dd = idx & 63;
        int tok = (widx - 1) * WS + jj;
        float v = (tok < 0) ? 0.f : vbase[(size_t)tok * QKVN + dd];
        __nv_bfloat16 hv = __float2bfloat16(v);
        uint32_t off = dd * PV_ROWB + jj * 2;
        *(__nv_bfloat16*)(sm + OFF_VH + off) = hv;
        *(__nv_bfloat16*)(sm + OFF_VL + off) = __float2bfloat16(v - __bfloat162float(hv));
    }
    __syncthreads();   // the ONLY barrier

    float acc[18][4];
#pragma unroll
    for (int nt = 0; nt < 18; nt++)
#pragma unroll
        for (int i = 0; i < 4; i++) acc[nt][i] = 0.f;

    const uint32_t lrq = (lane & 15) * QK_ROWB + (lane >> 4) * 16;
    const uint32_t lrp = (lane & 15) * PV_ROWB + (lane >> 4) * 16;

#pragma unroll
    for (int ks = 0; ks < 4; ks++) {
        const uint32_t ko = ks * 32;
        uint32_t ah[4], al_[4];
        ldm_x4(ah,  sb + OFF_QH + wid * 16 * QK_ROWB + ko + lrq);
        ldm_x4(al_, sb + OFF_QL + wid * 16 * QK_ROWB + ko + lrq);
#pragma unroll
        for (int t = 0; t < 9; t++) {
            uint32_t addr = sb + OFF_KH + (wid + t) * 16 * QK_ROWB + ko + lrq;
            uint32_t rh[4], rl[4];
            ldm_x4(rh, addr);
            ldm_x4(rl, addr + (OFF_KL - OFF_KH));
            uint32_t bh0[2] = {rh[0], rh[2]}, bh1[2] = {rh[1], rh[3]};
            uint32_t bl0[2] = {rl[0], rl[2]}, bl1[2] = {rl[1], rl[3]};
            mma16816(acc[2 * t],     ah, bh0);
            mma16816(acc[2 * t],     ah, bl0);
            mma16816(acc[2 * t],     al_, bh0);
            mma16816(acc[2 * t + 1], ah, bh1);
            mma16816(acc[2 * t + 1], ah, bl1);
            mma16816(acc[2 * t + 1], al_, bh1);
        }
    }

    const int q4 = lane & 3;
    const int cbase = 16 * wid;
    float inv[2];
#pragma unroll
    for (int i01 = 0; i01 < 2; i01++) {
        int r = wid * 16 + (lane >> 2) + i01 * 8;
        float mx = -1e30f;
#pragma unroll
        for (int nt = 0; nt < 18; nt++)
#pragma unroll
            for (int e = 0; e < 2; e++) {
                int c = cbase + 8 * nt + 2 * q4 + e;
                bool keep = (c >= r) && (c <= r + WS) && (widx > 0 || c >= WS);
                float& v = acc[nt][i01 * 2 + e];
                if (!keep) v = -1e30f;
                mx = fmaxf(mx, v);
            }
        mx = fmaxf(mx, __shfl_xor_sync(0xffffffffu, mx, 1));
        mx = fmaxf(mx, __shfl_xor_sync(0xffffffffu, mx, 2));
        float sum = 0.f;
#pragma unroll
        for (int nt = 0; nt < 18; nt++)
#pragma unroll
            for (int e = 0; e < 2; e++) {
                float& v = acc[nt][i01 * 2 + e];
                v = __expf(v - mx);
                sum += v;
            }
        sum += __shfl_xor_sync(0xffffffffu, sum, 1);
        sum += __shfl_xor_sync(0xffffffffu, sum, 2);
        inv[i01] = 1.0f / sum;
    }

    float o[8][4];
#pragma unroll
    for (int nt = 0; nt < 8; nt++)
#pragma unroll
        for (int i = 0; i < 4; i++) o[nt][i] = 0.f;

#pragma unroll
    for (int t = 0; t < 9; t++) {
        uint32_t ph[4], pl[4];
#pragma unroll
        for (int rr = 0; rr < 2; rr++) {
            const float* f = acc[2 * t + rr];
            uint32_t h0 = pack_bf16x2(f[0], f[1]);
            uint32_t h1 = pack_bf16x2(f[2], f[3]);
            __nv_bfloat162 hb0 = *(__nv_bfloat162*)&h0;
            __nv_bfloat162 hb1 = *(__nv_bfloat162*)&h1;
            ph[2 * rr]     = h0;
            ph[2 * rr + 1] = h1;
            pl[2 * rr]     = pack_bf16x2(f[0] - __bfloat162float(hb0.x),
                                         f[1] - __bfloat162float(hb0.y));
            pl[2 * rr + 1] = pack_bf16x2(f[2] - __bfloat162float(hb1.x),
                                         f[3] - __bfloat162float(hb1.y));
        }
        const uint32_t ko = (wid + t) * 32;
#pragma unroll
        for (int nt2 = 0; nt2 < 4; nt2++) {
            uint32_t addrB = sb + OFF_VH + nt2 * 16 * PV_ROWB + ko + lrp;
            uint32_t rh[4], rl[4];
            ldm_x4(rh, addrB);
            ldm_x4(rl, addrB + (OFF_VL - OFF_VH));
            uint32_t vh0[2] = {rh[0], rh[2]}, vh1[2] = {rh[1], rh[3]};
            uint32_t vl0[2] = {rl[0], rl[2]}, vl1[2] = {rl[1], rl[3]};
            mma16816(o[2 * nt2],     ph, vh0);
            mma16816(o[2 * nt2],     ph, vl0);
            mma16816(o[2 * nt2],     pl, vh0);
            mma16816(o[2 * nt2 + 1], ph, vh1);
            mma16816(o[2 * nt2 + 1], ph, vl1);
            mma16816(o[2 * nt2 + 1], pl, vh1);
        }
    }

    const int gr = lane >> 2;
#pragma unroll
    for (int i01 = 0; i01 < 2; i01++) {
        int row = widx * WS + wid * 16 + gr + i01 * 8;
        size_t base = (size_t)(bi * NTOK + row) * DIM + h * DH;
        float nrm = inv[i01];
#pragma unroll
        for (int nt = 0; nt < 8; nt++) {
            int col = nt * 8 + 2 * q4;
            float v0 = o[nt][i01 * 2] * nrm, v1 = o[nt][i01 * 2 + 1] * nrm;
            __nv_bfloat162 hv = __floats2bfloat162_rn(v0, v1);
            __nv_bfloat162 lv = __floats2bfloat162_rn(v0 - __bfloat162float(hv.x),
                                                      v1 - __bfloat162float(hv.y));
            *(__nv_bfloat162*)&g_ah[base + col] = hv;
            *(__nv_bfloat162*)&g_al[base + col] = lv;
        }
    }
}

// ---------------------------------------------------------------------------
extern "C" void kernel_launch(void* const* d_in, const int* in_sizes, int n_in,
                              void* d_out, int out_size)
{
    const float* x    = (const float*)d_in[0];
    const float* Wqkv = (const float*)d_in[1];
    const float* Wout = (const float*)d_in[2];
    float* out = (float*)d_out;

    float *qkv_p;
    __nv_bfloat16 *xh, *xl, *wqh, *wql, *woh, *wol, *ah, *al;
    cudaGetSymbolAddress((void**)&qkv_p, g_qkv);
    cudaGetSymbolAddress((void**)&xh, g_xh);   cudaGetSymbolAddress((void**)&xl, g_xl);
    cudaGetSymbolAddress((void**)&wqh, g_wqh); cudaGetSymbolAddress((void**)&wql, g_wql);
    cudaGetSymbolAddress((void**)&woh, g_woh); cudaGetSymbolAddress((void**)&wol, g_wol);
    cudaGetSymbolAddress((void**)&ah, g_ah);   cudaGetSymbolAddress((void**)&al, g_al);

    cudaFuncSetAttribute(gemm_bf16x3,
                         cudaFuncAttributeMaxDynamicSharedMemorySize, GSMEM_BYTES);
    cudaFuncSetAttribute(attn_mma_kernel,
                         cudaFuncAttributeMaxDynamicSharedMemorySize, ASMEM_BYTES);

    rope_table_kernel<<<32, 256>>>();
    split_f32<<<(MTOT * DIM / 4 + 255) / 256, 256>>>(x, xh, xl, MTOT * DIM / 4);
    transpose_split<<<dim3(QKVN / 32, DIM / 32), 256>>>(Wqkv, wqh, wql, DIM, QKVN);
    transpose_split<<<dim3(DIM / 32, DIM / 32), 256>>>(Wout, woh, wol, DIM, DIM);

    gemm_bf16x3<<<dim3(QKVN / 128, MTOT / 128), 128, GSMEM_BYTES>>>(
        xh, xl, wqh, wql, qkv_p, MTOT, QKVN, DIM);

    attn_mma_kernel<<<dim3(NWIN, NHEAD, BATCH), 256, ASMEM_BYTES>>>();

    gemm_bf16x3<<<dim3(DIM / 128, MTOT / 128), 128, GSMEM_BYTES>>>(
        ah, al, woh, wol, out, MTOT, DIM, DIM);
}

// round 14
// speedup vs baseline: 1.2904x; 1.2904x over previous
#include <cuda_runtime.h>
#include <cuda_bf16.h>
#include <cuda_fp16.h>
#include <math.h>
#include <stdint.h>

#define BATCH 4
#define NTOK  4096
#define DIM   1024
#define NHEAD 16
#define DH    64
#define WS    128
#define NWIN  32
#define QKVN  3072
#define MTOT  (BATCH * NTOK)   // 16384

// ---------------------------------------------------------------------------
// Scratch (static device globals: allocation-free, graph-capturable)
// ---------------------------------------------------------------------------
__device__ float    g_qkv [(size_t)MTOT * QKVN];      // f32 q|k|v
__device__ __half   g_xh  [(size_t)MTOT * DIM];       // x split hi (fp16)
__device__ __half   g_xl  [(size_t)MTOT * DIM];       // x split lo (fp16)
__device__ __half   g_wq  [(size_t)QKVN * DIM];       // Wqkv^T fp16 (unsplit)
__device__ __half   g_wo  [(size_t)DIM * DIM];        // Wout^T fp16 (unsplit)
__device__ __half   g_ah  [(size_t)MTOT * DIM];       // attn out hi (fp16)
__device__ __half   g_al  [(size_t)MTOT * DIM];       // attn out lo (fp16)
__device__ float2   g_rope[256 * 32];                 // (sin, cos) per (pos, d)

// ---------------------------------------------------------------------------
// Base-target primitives (compute_103 rejects tcgen05; mma.sync is legal)
// ---------------------------------------------------------------------------
__device__ __forceinline__ uint32_t smem_u32(const void* p) {
    return (uint32_t)__cvta_generic_to_shared(p);
}
__device__ __forceinline__ void cp_async16(uint32_t saddr, const void* gaddr) {
    asm volatile("cp.async.cg.shared.global [%0], [%1], 16;" :: "r"(saddr), "l"(gaddr));
}
#define CP_COMMIT()  asm volatile("cp.async.commit_group;" ::: "memory")
#define CP_WAIT(N)   asm volatile("cp.async.wait_group %0;" :: "n"(N) : "memory")

__device__ __forceinline__ void ldm_x4(uint32_t* r, uint32_t addr) {
    asm volatile("ldmatrix.sync.aligned.m8n8.x4.shared.b16 {%0,%1,%2,%3}, [%4];"
                 : "=r"(r[0]), "=r"(r[1]), "=r"(r[2]), "=r"(r[3]) : "r"(addr));
}
// bf16 mma (attention)
__device__ __forceinline__ void mma16816(float* c, const uint32_t* a, const uint32_t* b) {
    asm volatile("mma.sync.aligned.m16n8k16.row.col.f32.bf16.bf16.f32 "
                 "{%0,%1,%2,%3}, {%4,%5,%6,%7}, {%8,%9}, {%0,%1,%2,%3};"
                 : "+f"(c[0]), "+f"(c[1]), "+f"(c[2]), "+f"(c[3])
                 : "r"(a[0]), "r"(a[1]), "r"(a[2]), "r"(a[3]), "r"(b[0]), "r"(b[1]));
}
// fp16 mma (GEMMs)
__device__ __forceinline__ void mma16816h(float* c, const uint32_t* a, const uint32_t* b) {
    asm volatile("mma.sync.aligned.m16n8k16.row.col.f32.f16.f16.f32 "
                 "{%0,%1,%2,%3}, {%4,%5,%6,%7}, {%8,%9}, {%0,%1,%2,%3};"
                 : "+f"(c[0]), "+f"(c[1]), "+f"(c[2]), "+f"(c[3])
                 : "r"(a[0]), "r"(a[1]), "r"(a[2]), "r"(a[3]), "r"(b[0]), "r"(b[1]));
}
__device__ __forceinline__ uint32_t pack_bf16x2(float a, float b) {
    __nv_bfloat162 h = __floats2bfloat162_rn(a, b);
    uint32_t u; *(__nv_bfloat162*)&u = h;
    return u;
}

// ---------------------------------------------------------------------------
// Prep kernels
// ---------------------------------------------------------------------------
__global__ __launch_bounds__(256) void rope_table_kernel()
{
    int idx = blockIdx.x * 256 + threadIdx.x;
    if (idx >= 256 * 32) return;
    int j = idx >> 5, d = idx & 31;
    float inv_freq = expf(-logf(10000.0f) * (float)d * (1.0f / 32.0f));
    float s, c;
    sincosf((float)j * inv_freq, &s, &c);
    g_rope[idx] = make_float2(s, c);
}

// x f32 -> fp16 hi/lo
__global__ __launch_bounds__(256) void split_f32h(const float* __restrict__ src,
                                                  __half* __restrict__ hi,
                                                  __half* __restrict__ lo, int n4)
{
    int i = blockIdx.x * 256 + threadIdx.x;
    if (i >= n4) return;
    float4 v = ((const float4*)src)[i];
    float a[4] = {v.x, v.y, v.z, v.w};
#pragma unroll
    for (int j = 0; j < 4; j++) {
        __half h = __float2half_rn(a[j]);
        hi[i * 4 + j] = h;
        lo[i * 4 + j] = __float2half_rn(a[j] - __half2float(h));
    }
}

// W[K][N] f32 -> T[N][K] fp16 (unsplit)
__global__ __launch_bounds__(256) void transpose_h(const float* __restrict__ W,
                                                   __half* __restrict__ T,
                                                   int K, int N)
{
    __shared__ float t[32][33];
    int n0 = blockIdx.x * 32, k0 = blockIdx.y * 32;
    int tx = threadIdx.x & 31, ty8 = threadIdx.x >> 5;
#pragma unroll
    for (int r = 0; r < 4; r++) {
        int ky = ty8 + r * 8;
        t[ky][tx] = W[(size_t)(k0 + ky) * N + n0 + tx];
    }
    __syncthreads();
#pragma unroll
    for (int r = 0; r < 4; r++) {
        int ny = ty8 + r * 8;
        T[(size_t)(n0 + ny) * K + k0 + tx] = __float2half_rn(t[tx][ny]);
    }
}

// ---------------------------------------------------------------------------
// fp16x2 GEMM: C = (Ah+Al)[M,K] @ B[N,K]^T,  2 MMAs per k-step (vs 3 before).
// 128x128 CTA tile, 128 threads / 4 warps (each 64x64), KC=32,
// XOR-swizzled 64B rows, 3-stage cp.async, ONE barrier/chunk, 2 CTAs/SM.
// ---------------------------------------------------------------------------
#define KC       32
#define ARR_B    8192
#define STAGE_B  (3 * ARR_B)           // 24576 (Ah | Al | B)
#define GSMEM_BYTES (3 * STAGE_B)      // 73728 (x2 CTAs = 147456)

__device__ __forceinline__ uint32_t sw_off(int row, int c16) {
    return (uint32_t)(((row >> 1) << 7) + ((row & 1) << 6)
                      + (((c16 ^ (row >> 1)) & 3) << 4));
}

__global__ __launch_bounds__(128, 2) void gemm_fp16x2(
    const __half* __restrict__ Ah, const __half* __restrict__ Al,
    const __half* __restrict__ B,
    float* __restrict__ C, int M, int N, int K)
{
    extern __shared__ char sm[];
    const uint32_t sbase = smem_u32(sm);
    const int tid  = threadIdx.x;
    const int wid  = tid >> 5;           // 0..3
    const int lane = tid & 31;
    const int wr   = (wid >> 1) * 64;    // 0 / 64
    const int wc   = (wid & 1) * 64;     // 0 / 64

    const int r0 = blockIdx.y * 128;
    const int c0 = blockIdx.x * 128;

    const __half* gsrc[3] = {
        Ah + (size_t)r0 * K, Al + (size_t)r0 * K, B + (size_t)c0 * K };

    const int ldrow = tid >> 2;          // 0..31
    const int ldseg = tid & 3;           // 0..3

    auto issue = [&](int kc, int s) {
        const uint32_t stb = sbase + s * STAGE_B;
#pragma unroll
        for (int t = 0; t < 3; t++) {
#pragma unroll
            for (int q = 0; q < 4; q++) {
                int row = ldrow + q * 32;
                const void* g = gsrc[t] + (size_t)row * K + kc * KC + ldseg * 8;
                cp_async16(stb + t * ARR_B + sw_off(row, ldseg), g);
            }
        }
    };

    float acc[4][8][4];
#pragma unroll
    for (int mt = 0; mt < 4; mt++)
#pragma unroll
        for (int nt = 0; nt < 8; nt++)
#pragma unroll
            for (int i = 0; i < 4; i++) acc[mt][nt][i] = 0.f;

    const int rl = lane & 15, chh = lane >> 4;
    const uint32_t ltb = (uint32_t)(((rl >> 1) << 7) + ((rl & 1) << 6));
    const uint32_t lt0 = ltb + ((((chh)     ^ (rl >> 1)) & 3) << 4);
    const uint32_t lt1 = ltb + ((((2 + chh) ^ (rl >> 1)) & 3) << 4);

    const int nchunk = K / KC;
    issue(0, 0); CP_COMMIT();
    issue(1, 1); CP_COMMIT();

    int buf = 0;
    for (int kc = 0; kc < nchunk; kc++) {
        if (kc + 1 < nchunk) CP_WAIT(1); else CP_WAIT(0);
        __syncthreads();
        if (kc + 2 < nchunk) {
            int nb = buf + 2; if (nb >= 3) nb -= 3;
            issue(kc + 2, nb);
            CP_COMMIT();
        }

        const uint32_t stb = sbase + buf * STAGE_B;
#pragma unroll
        for (int ks = 0; ks < 2; ks++) {
            const uint32_t lt = ks ? lt1 : lt0;
            uint32_t ah[4][4], al_[4][4];
#pragma unroll
            for (int mt = 0; mt < 4; mt++) {
                uint32_t ra = (uint32_t)(wr + mt * 16) * 64 + lt;
                ldm_x4(ah[mt],  stb + 0 * ARR_B + ra);
                ldm_x4(al_[mt], stb + 1 * ARR_B + ra);
            }
            uint32_t b[8][2];
#pragma unroll
            for (int nh = 0; nh < 4; nh++) {
                uint32_t rb = (uint32_t)(wc + nh * 16) * 64 + lt;
                uint32_t r[4];
                ldm_x4(r, stb + 2 * ARR_B + rb);
                b[nh * 2][0] = r[0]; b[nh * 2][1] = r[2];
                b[nh * 2 + 1][0] = r[1]; b[nh * 2 + 1][1] = r[3];
            }
#pragma unroll
            for (int mt = 0; mt < 4; mt++)
#pragma unroll
                for (int nt = 0; nt < 8; nt++) {
                    mma16816h(acc[mt][nt], ah[mt],  b[nt]);
                    mma16816h(acc[mt][nt], al_[mt], b[nt]);
                }
        }
        if (++buf == 3) buf = 0;
    }

    const int gr = lane >> 2;
    const int gc = (lane & 3) * 2;
#pragma unroll
    for (int mt = 0; mt < 4; mt++) {
        int row = r0 + wr + mt * 16 + gr;
#pragma unroll
        for (int nt = 0; nt < 8; nt++) {
            int col = c0 + wc + nt * 8 + gc;
            *(float2*)&C[(size_t)row * N + col] =
                make_float2(acc[mt][nt][0], acc[mt][nt][1]);
            *(float2*)&C[(size_t)(row + 8) * N + col] =
                make_float2(acc[mt][nt][2], acc[mt][nt][3]);
        }
    }
}

// ---------------------------------------------------------------------------
// Tensor-core local attention, mask-aware, P in registers, bf16x3 internally
// (unchanged — keeps mid-chain error ~1e-5). Epilogue now writes fp16 hi/lo.
// ---------------------------------------------------------------------------
#define QK_ROWB 144
#define PV_ROWB 528
#define OFF_QH  0
#define OFF_QL  18432
#define OFF_KH  36864
#define OFF_KL  73728
#define OFF_VH  110592
#define OFF_VL  144384
#define ASMEM_BYTES 178176

__global__ __launch_bounds__(256) void attn_mma_kernel()
{
    extern __shared__ char sm[];
    const uint32_t sb = smem_u32(sm);

    const int widx = blockIdx.x;
    const int h    = blockIdx.y;
    const int bi   = blockIdx.z;
    const int tid  = threadIdx.x;
    const int wid  = tid >> 5;
    const int lane = tid & 31;
    const int d    = tid & 31;
    const int grp  = tid >> 5;

    const float scale = 0.125f;

    const float* qbase = g_qkv + (size_t)(bi * NTOK + widx * WS) * QKVN + h * DH;
#pragma unroll 4
    for (int it = 0; it < 16; it++) {
        int i = grp + 8 * it;
        const float* p = qbase + (size_t)i * QKVN;
        float x1 = p[d], x2 = p[d + 32];
        float2 sc = g_rope[(WS + i) * 32 + d];
        float v1 = (x1 * sc.y - x2 * sc.x) * scale;
        float v2 = (x2 * sc.y + x1 * sc.x) * scale;
        uint32_t row = i * QK_ROWB;
        __nv_bfloat16 b1 = __float2bfloat16(v1), b2 = __float2bfloat16(v2);
        *(__nv_bfloat16*)(sm + OFF_QH + row + d * 2)        = b1;
        *(__nv_bfloat16*)(sm + OFF_QH + row + (d + 32) * 2) = b2;
        *(__nv_bfloat16*)(sm + OFF_QL + row + d * 2)        = __float2bfloat16(v1 - __bfloat162float(b1));
        *(__nv_bfloat16*)(sm + OFF_QL + row + (d + 32) * 2) = __float2bfloat16(v2 - __bfloat162float(b2));
    }
    const float* kbase = g_qkv + (size_t)(bi * NTOK) * QKVN + DIM + h * DH;
#pragma unroll 4
    for (int it = 0; it < 32; it++) {
        int jj  = grp + 8 * it;
        int tok = (widx - 1) * WS + jj;
        float x1 = 0.f, x2 = 0.f;
        if (tok >= 0) {
            const float* p = kbase + (size_t)tok * QKVN;
            x1 = p[d]; x2 = p[d + 32];
        }
        float2 sc = g_rope[jj * 32 + d];
        float v1 = x1 * sc.y - x2 * sc.x;
        float v2 = x2 * sc.y + x1 * sc.x;
        uint32_t row = jj * QK_ROWB;
        __nv_bfloat16 b1 = __float2bfloat16(v1), b2 = __float2bfloat16(v2);
        *(__nv_bfloat16*)(sm + OFF_KH + row + d * 2)        = b1;
        *(__nv_bfloat16*)(sm + OFF_KH + row + (d + 32) * 2) = b2;
        *(__nv_bfloat16*)(sm + OFF_KL + row + d * 2)        = __float2bfloat16(v1 - __bfloat162float(b1));
        *(__nv_bfloat16*)(sm + OFF_KL + row + (d + 32) * 2) = __float2bfloat16(v2 - __bfloat162float(b2));
    }
    const float* vbase = g_qkv + (size_t)(bi * NTOK) * QKVN + 2 * DIM + h * DH;
    for (int idx = tid; idx < 256 * 64; idx += 256) {
        int jj = idx >> 6, dd = idx & 63;
        int tok = (widx - 1) * WS + jj;
        float v = (tok < 0) ? 0.f : vbase[(size_t)tok * QKVN + dd];
        __nv_bfloat16 hv = __float2bfloat16(v);
        uint32_t off = dd * PV_ROWB + jj * 2;
        *(__nv_bfloat16*)(sm + OFF_VH + off) = hv;
        *(__nv_bfloat16*)(sm + OFF_VL + off) = __float2bfloat16(v - __bfloat162float(hv));
    }
    __syncthreads();   // the ONLY barrier

    float acc[18][4];
#pragma unroll
    for (int nt = 0; nt < 18; nt++)
#pragma unroll
        for (int i = 0; i < 4; i++) acc[nt][i] = 0.f;

    const uint32_t lrq = (lane & 15) * QK_ROWB + (lane >> 4) * 16;
    const uint32_t lrp = (lane & 15) * PV_ROWB + (lane >> 4) * 16;

#pragma unroll
    for (int ks = 0; ks < 4; ks++) {
        const uint32_t ko = ks * 32;
        uint32_t ah[4], al_[4];
        ldm_x4(ah,  sb + OFF_QH + wid * 16 * QK_ROWB + ko + lrq);
        ldm_x4(al_, sb + OFF_QL + wid * 16 * QK_ROWB + ko + lrq);
#pragma unroll
        for (int t = 0; t < 9; t++) {
            uint32_t addr = sb + OFF_KH + (wid + t) * 16 * QK_ROWB + ko + lrq;
            uint32_t rh[4], rl[4];
            ldm_x4(rh, addr);
            ldm_x4(rl, addr + (OFF_KL - OFF_KH));
            uint32_t bh0[2] = {rh[0], rh[2]}, bh1[2] = {rh[1], rh[3]};
            uint32_t bl0[2] = {rl[0], rl[2]}, bl1[2] = {rl[1], rl[3]};
            mma16816(acc[2 * t],     ah, bh0);
            mma16816(acc[2 * t],     ah, bl0);
            mma16816(acc[2 * t],     al_, bh0);
            mma16816(acc[2 * t + 1], ah, bh1);
            mma16816(acc[2 * t + 1], ah, bl1);
            mma16816(acc[2 * t + 1], al_, bh1);
        }
    }

    const int q4 = lane & 3;
    const int cbase = 16 * wid;
    float inv[2];
#pragma unroll
    for (int i01 = 0; i01 < 2; i01++) {
        int r = wid * 16 + (lane >> 2) + i01 * 8;
        float mx = -1e30f;
#pragma unroll
        for (int nt = 0; nt < 18; nt++)
#pragma unroll
            for (int e = 0; e < 2; e++) {
                int c = cbase + 8 * nt + 2 * q4 + e;
                bool keep = (c >= r) && (c <= r + WS) && (widx > 0 || c >= WS);
                float& v = acc[nt][i01 * 2 + e];
                if (!keep) v = -1e30f;
                mx = fmaxf(mx, v);
            }
        mx = fmaxf(mx, __shfl_xor_sync(0xffffffffu, mx, 1));
        mx = fmaxf(mx, __shfl_xor_sync(0xffffffffu, mx, 2));
        float sum = 0.f;
#pragma unroll
        for (int nt = 0; nt < 18; nt++)
#pragma unroll
            for (int e = 0; e < 2; e++) {
                float& v = acc[nt][i01 * 2 + e];
                v = __expf(v - mx);
                sum += v;
            }
        sum += __shfl_xor_sync(0xffffffffu, sum, 1);
        sum += __shfl_xor_sync(0xffffffffu, sum, 2);
        inv[i01] = 1.0f / sum;
    }

    float o[8][4];
#pragma unroll
    for (int nt = 0; nt < 8; nt++)
#pragma unroll
        for (int i = 0; i < 4; i++) o[nt][i] = 0.f;

#pragma unroll
    for (int t = 0; t < 9; t++) {
        uint32_t ph[4], pl[4];
#pragma unroll
        for (int rr = 0; rr < 2; rr++) {
            const float* f = acc[2 * t + rr];
            uint32_t h0 = pack_bf16x2(f[0], f[1]);
            uint32_t h1 = pack_bf16x2(f[2], f[3]);
            __nv_bfloat162 hb0 = *(__nv_bfloat162*)&h0;
            __nv_bfloat162 hb1 = *(__nv_bfloat162*)&h1;
            ph[2 * rr]     = h0;
            ph[2 * rr + 1] = h1;
            pl[2 * rr]     = pack_bf16x2(f[0] - __bfloat162float(hb0.x),
                                         f[1] - __bfloat162float(hb0.y));
            pl[2 * rr + 1] = pack_bf16x2(f[2] - __bfloat162float(hb1.x),
                                         f[3] - __bfloat162float(hb1.y));
        }
        const uint32_t ko = (wid + t) * 32;
#pragma unroll
        for (int nt2 = 0; nt2 < 4; nt2++) {
            uint32_t addrB = sb + OFF_VH + nt2 * 16 * PV_ROWB + ko + lrp;
            uint32_t rh[4], rl[4];
            ldm_x4(rh, addrB);
            ldm_x4(rl, addrB + (OFF_VL - OFF_VH));
            uint32_t vh0[2] = {rh[0], rh[2]}, vh1[2] = {rh[1], rh[3]};
            uint32_t vl0[2] = {rl[0], rl[2]}, vl1[2] = {rl[1], rl[3]};
            mma16816(o[2 * nt2],     ph, vh0);
            mma16816(o[2 * nt2],     ph, vl0);
            mma16816(o[2 * nt2],     pl, vh0);
            mma16816(o[2 * nt2 + 1], ph, vh1);
            mma16816(o[2 * nt2 + 1], ph, vl1);
            mma16816(o[2 * nt2 + 1], pl, vh1);
        }
    }

    // ---- epilogue: normalize rows, write fp16 hi/lo (feeds fp16x2 GEMM2) ----
    const int gr = lane >> 2;
#pragma unroll
    for (int i01 = 0; i01 < 2; i01++) {
        int row = widx * WS + wid * 16 + gr + i01 * 8;
        size_t base = (size_t)(bi * NTOK + row) * DIM + h * DH;
        float nrm = inv[i01];
#pragma unroll
        for (int nt = 0; nt < 8; nt++) {
            int col = nt * 8 + 2 * q4;
            float v0 = o[nt][i01 * 2] * nrm, v1 = o[nt][i01 * 2 + 1] * nrm;
            __half2 hv = __floats2half2_rn(v0, v1);
            __half2 lv = __floats2half2_rn(v0 - __half2float(__low2half(hv)),
                                           v1 - __half2float(__high2half(hv)));
            *(__half2*)&g_ah[base + col] = hv;
            *(__half2*)&g_al[base + col] = lv;
        }
    }
}

// ---------------------------------------------------------------------------
extern "C" void kernel_launch(void* const* d_in, const int* in_sizes, int n_in,
                              void* d_out, int out_size)
{
    const float* x    = (const float*)d_in[0];
    const float* Wqkv = (const float*)d_in[1];
    const float* Wout = (const float*)d_in[2];
    float* out = (float*)d_out;

    float *qkv_p;
    __half *xh, *xl, *wq, *wo, *ah, *al;
    cudaGetSymbolAddress((void**)&qkv_p, g_qkv);
    cudaGetSymbolAddress((void**)&xh, g_xh); cudaGetSymbolAddress((void**)&xl, g_xl);
    cudaGetSymbolAddress((void**)&wq, g_wq); cudaGetSymbolAddress((void**)&wo, g_wo);
    cudaGetSymbolAddress((void**)&ah, g_ah); cudaGetSymbolAddress((void**)&al, g_al);

    cudaFuncSetAttribute(gemm_fp16x2,
                         cudaFuncAttributeMaxDynamicSharedMemorySize, GSMEM_BYTES);
    cudaFuncSetAttribute(attn_mma_kernel,
                         cudaFuncAttributeMaxDynamicSharedMemorySize, ASMEM_BYTES);

    rope_table_kernel<<<32, 256>>>();
    split_f32h<<<(MTOT * DIM / 4 + 255) / 256, 256>>>(x, xh, xl, MTOT * DIM / 4);
    transpose_h<<<dim3(QKVN / 32, DIM / 32), 256>>>(Wqkv, wq, DIM, QKVN);
    transpose_h<<<dim3(DIM / 32, DIM / 32), 256>>>(Wout, wo, DIM, DIM);

    // 1) qkv = x @ Wqkv   (fp16x2: 2 MMAs per k-step)
    gemm_fp16x2<<<dim3(QKVN / 128, MTOT / 128), 128, GSMEM_BYTES>>>(
        xh, xl, wq, qkv_p, MTOT, QKVN, DIM);

    // 2) local attention (bf16x3 inside, fp16 hi/lo out)
    attn_mma_kernel<<<dim3(NWIN, NHEAD, BATCH), 256, ASMEM_BYTES>>>();

    // 3) out = attn @ Wout (fp16x2)
    gemm_fp16x2<<<dim3(DIM / 128, MTOT / 128), 128, GSMEM_BYTES>>>(
        ah, al, wo, out, MTOT, DIM, DIM);
}

// round 15
// speedup vs baseline: 1.4958x; 1.1592x over previous
#include <cuda_runtime.h>
#include <cuda_bf16.h>
#include <cuda_fp16.h>
#include <math.h>
#include <stdint.h>

#define BATCH 4
#define NTOK  4096
#define DIM   1024
#define NHEAD 16
#define DH    64
#define WS    128
#define NWIN  32
#define QKVN  3072
#define MTOT  (BATCH * NTOK)   // 16384

// ---------------------------------------------------------------------------
// Scratch (static device globals: allocation-free, graph-capturable)
// ---------------------------------------------------------------------------
__device__ float    g_qkv [(size_t)MTOT * QKVN];      // f32 q|k|v
__device__ __half   g_xh  [(size_t)MTOT * DIM];       // x split hi (fp16)
__device__ __half   g_xl  [(size_t)MTOT * DIM];       // x split lo (fp16)
__device__ __half   g_wq  [(size_t)QKVN * DIM];       // Wqkv^T fp16
__device__ __half   g_wo  [(size_t)DIM * DIM];        // Wout^T fp16
__device__ __half   g_ah  [(size_t)MTOT * DIM];       // attn out hi (fp16)
__device__ __half   g_al  [(size_t)MTOT * DIM];       // attn out lo (fp16)
__device__ float2   g_rope[256 * 32];                 // (sin, cos) per (pos, d)

// ---------------------------------------------------------------------------
// Base-target primitives (compute_103 rejects tcgen05; mma.sync is legal)
// ---------------------------------------------------------------------------
__device__ __forceinline__ uint32_t smem_u32(const void* p) {
    return (uint32_t)__cvta_generic_to_shared(p);
}
__device__ __forceinline__ void cp_async16(uint32_t saddr, const void* gaddr) {
    asm volatile("cp.async.cg.shared.global [%0], [%1], 16;" :: "r"(saddr), "l"(gaddr));
}
#define CP_COMMIT()  asm volatile("cp.async.commit_group;" ::: "memory")
#define CP_WAIT(N)   asm volatile("cp.async.wait_group %0;" :: "n"(N) : "memory")

__device__ __forceinline__ void ldm_x4(uint32_t* r, uint32_t addr) {
    asm volatile("ldmatrix.sync.aligned.m8n8.x4.shared.b16 {%0,%1,%2,%3}, [%4];"
                 : "=r"(r[0]), "=r"(r[1]), "=r"(r[2]), "=r"(r[3]) : "r"(addr));
}
// fp16 mma (GEMMs + attention)
__device__ __forceinline__ void mma16816h(float* c, const uint32_t* a, const uint32_t* b) {
    asm volatile("mma.sync.aligned.m16n8k16.row.col.f32.f16.f16.f32 "
                 "{%0,%1,%2,%3}, {%4,%5,%6,%7}, {%8,%9}, {%0,%1,%2,%3};"
                 : "+f"(c[0]), "+f"(c[1]), "+f"(c[2]), "+f"(c[3])
                 : "r"(a[0]), "r"(a[1]), "r"(a[2]), "r"(a[3]), "r"(b[0]), "r"(b[1]));
}
__device__ __forceinline__ uint32_t pack_half2(float a, float b) {
    __half2 h = __floats2half2_rn(a, b);
    uint32_t u; *(__half2*)&u = h;
    return u;
}

// ---------------------------------------------------------------------------
// Prep kernels
// ---------------------------------------------------------------------------
__global__ __launch_bounds__(256) void rope_table_kernel()
{
    int idx = blockIdx.x * 256 + threadIdx.x;
    if (idx >= 256 * 32) return;
    int j = idx >> 5, d = idx & 31;
    float inv_freq = expf(-logf(10000.0f) * (float)d * (1.0f / 32.0f));
    float s, c;
    sincosf((float)j * inv_freq, &s, &c);
    g_rope[idx] = make_float2(s, c);
}

__global__ __launch_bounds__(256) void split_f32h(const float* __restrict__ src,
                                                  __half* __restrict__ hi,
                                                  __half* __restrict__ lo, int n4)
{
    int i = blockIdx.x * 256 + threadIdx.x;
    if (i >= n4) return;
    float4 v = ((const float4*)src)[i];
    float a[4] = {v.x, v.y, v.z, v.w};
#pragma unroll
    for (int j = 0; j < 4; j++) {
        __half h = __float2half_rn(a[j]);
        hi[i * 4 + j] = h;
        lo[i * 4 + j] = __float2half_rn(a[j] - __half2float(h));
    }
}

__global__ __launch_bounds__(256) void transpose_h(const float* __restrict__ W,
                                                   __half* __restrict__ T,
                                                   int K, int N)
{
    __shared__ float t[32][33];
    int n0 = blockIdx.x * 32, k0 = blockIdx.y * 32;
    int tx = threadIdx.x & 31, ty8 = threadIdx.x >> 5;
#pragma unroll
    for (int r = 0; r < 4; r++) {
        int ky = ty8 + r * 8;
        t[ky][tx] = W[(size_t)(k0 + ky) * N + n0 + tx];
    }
    __syncthreads();
#pragma unroll
    for (int r = 0; r < 4; r++) {
        int ny = ty8 + r * 8;
        T[(size_t)(n0 + ny) * K + k0 + tx] = __float2half_rn(t[tx][ny]);
    }
}

// ---------------------------------------------------------------------------
// fp16x2 GEMM: C = (Ah+Al)[M,K] @ B[N,K]^T  (round-14 config, unchanged)
// 128x128 CTA tile, 128 threads / 4 warps (each 64x64), KC=32,
// XOR-swizzled 64B rows, 3-stage cp.async, ONE barrier/chunk, 2 CTAs/SM.
// ---------------------------------------------------------------------------
#define KC       32
#define ARR_B    8192
#define STAGE_B  (3 * ARR_B)           // 24576 (Ah | Al | B)
#define GSMEM_BYTES (3 * STAGE_B)      // 73728

__device__ __forceinline__ uint32_t sw_off(int row, int c16) {
    return (uint32_t)(((row >> 1) << 7) + ((row & 1) << 6)
                      + (((c16 ^ (row >> 1)) & 3) << 4));
}

__global__ __launch_bounds__(128, 2) void gemm_fp16x2(
    const __half* __restrict__ Ah, const __half* __restrict__ Al,
    const __half* __restrict__ B,
    float* __restrict__ C, int M, int N, int K)
{
    extern __shared__ char sm[];
    const uint32_t sbase = smem_u32(sm);
    const int tid  = threadIdx.x;
    const int wid  = tid >> 5;
    const int lane = tid & 31;
    const int wr   = (wid >> 1) * 64;
    const int wc   = (wid & 1) * 64;

    const int r0 = blockIdx.y * 128;
    const int c0 = blockIdx.x * 128;

    const __half* gsrc[3] = {
        Ah + (size_t)r0 * K, Al + (size_t)r0 * K, B + (size_t)c0 * K };

    const int ldrow = tid >> 2;
    const int ldseg = tid & 3;

    auto issue = [&](int kc, int s) {
        const uint32_t stb = sbase + s * STAGE_B;
#pragma unroll
        for (int t = 0; t < 3; t++) {
#pragma unroll
            for (int q = 0; q < 4; q++) {
                int row = ldrow + q * 32;
                const void* g = gsrc[t] + (size_t)row * K + kc * KC + ldseg * 8;
                cp_async16(stb + t * ARR_B + sw_off(row, ldseg), g);
            }
        }
    };

    float acc[4][8][4];
#pragma unroll
    for (int mt = 0; mt < 4; mt++)
#pragma unroll
        for (int nt = 0; nt < 8; nt++)
#pragma unroll
            for (int i = 0; i < 4; i++) acc[mt][nt][i] = 0.f;

    const int rl = lane & 15, chh = lane >> 4;
    const uint32_t ltb = (uint32_t)(((rl >> 1) << 7) + ((rl & 1) << 6));
    const uint32_t lt0 = ltb + ((((chh)     ^ (rl >> 1)) & 3) << 4);
    const uint32_t lt1 = ltb + ((((2 + chh) ^ (rl >> 1)) & 3) << 4);

    const int nchunk = K / KC;
    issue(0, 0); CP_COMMIT();
    issue(1, 1); CP_COMMIT();

    int buf = 0;
    for (int kc = 0; kc < nchunk; kc++) {
        if (kc + 1 < nchunk) CP_WAIT(1); else CP_WAIT(0);
        __syncthreads();
        if (kc + 2 < nchunk) {
            int nb = buf + 2; if (nb >= 3) nb -= 3;
            issue(kc + 2, nb);
            CP_COMMIT();
        }

        const uint32_t stb = sbase + buf * STAGE_B;
#pragma unroll
        for (int ks = 0; ks < 2; ks++) {
            const uint32_t lt = ks ? lt1 : lt0;
            uint32_t ah[4][4], al_[4][4];
#pragma unroll
            for (int mt = 0; mt < 4; mt++) {
                uint32_t ra = (uint32_t)(wr + mt * 16) * 64 + lt;
                ldm_x4(ah[mt],  stb + 0 * ARR_B + ra);
                ldm_x4(al_[mt], stb + 1 * ARR_B + ra);
            }
            uint32_t b[8][2];
#pragma unroll
            for (int nh = 0; nh < 4; nh++) {
                uint32_t rb = (uint32_t)(wc + nh * 16) * 64 + lt;
                uint32_t r[4];
                ldm_x4(r, stb + 2 * ARR_B + rb);
                b[nh * 2][0] = r[0]; b[nh * 2][1] = r[2];
                b[nh * 2 + 1][0] = r[1]; b[nh * 2 + 1][1] = r[3];
            }
#pragma unroll
            for (int mt = 0; mt < 4; mt++)
#pragma unroll
                for (int nt = 0; nt < 8; nt++) {
                    mma16816h(acc[mt][nt], ah[mt],  b[nt]);
                    mma16816h(acc[mt][nt], al_[mt], b[nt]);
                }
        }
        if (++buf == 3) buf = 0;
    }

    const int gr = lane >> 2;
    const int gc = (lane & 3) * 2;
#pragma unroll
    for (int mt = 0; mt < 4; mt++) {
        int row = r0 + wr + mt * 16 + gr;
#pragma unroll
        for (int nt = 0; nt < 8; nt++) {
            int col = c0 + wc + nt * 8 + gc;
            *(float2*)&C[(size_t)row * N + col] =
                make_float2(acc[mt][nt][0], acc[mt][nt][1]);
            *(float2*)&C[(size_t)(row + 8) * N + col] =
                make_float2(acc[mt][nt][2], acc[mt][nt][3]);
        }
    }
}

// ---------------------------------------------------------------------------
// fp16 tensor-core local attention, mask-aware, P in registers.
// S = (Qh+Ql)·K  (Q split fp16, K unsplit fp16): 4 MMAs per 16-col tile.
// O = P·V       (P unsplit fp16, V unsplit fp16): 2 MMAs per 16-col n-tile.
// Total MMA count halved vs bf16x3 version. One __syncthreads.
// ---------------------------------------------------------------------------
#define QK_ROWB 144
#define PV_ROWB 528
#define OFF_QH  0
#define OFF_QL  18432                  // 128*144
#define OFF_K   36864                  // +128*144
#define OFF_V   73728                  // +256*144
#define ASMEM_BYTES 107520             // +64*528

__global__ __launch_bounds__(256) void attn_mma_kernel()
{
    extern __shared__ char sm[];
    const uint32_t sb = smem_u32(sm);

    const int widx = blockIdx.x;
    const int h    = blockIdx.y;
    const int bi   = blockIdx.z;
    const int tid  = threadIdx.x;
    const int wid  = tid >> 5;
    const int lane = tid & 31;
    const int d    = tid & 31;
    const int grp  = tid >> 5;

    const float scale = 0.125f;

    // ---- load Q (+scale +RoPE) -> fp16 hi/lo ----
    const float* qbase = g_qkv + (size_t)(bi * NTOK + widx * WS) * QKVN + h * DH;
#pragma unroll 4
    for (int it = 0; it < 16; it++) {
        int i = grp + 8 * it;
        const float* p = qbase + (size_t)i * QKVN;
        float x1 = p[d], x2 = p[d + 32];
        float2 sc = g_rope[(WS + i) * 32 + d];
        float v1 = (x1 * sc.y - x2 * sc.x) * scale;
        float v2 = (x2 * sc.y + x1 * sc.x) * scale;
        uint32_t row = i * QK_ROWB;
        __half h1 = __float2half_rn(v1), h2 = __float2half_rn(v2);
        *(__half*)(sm + OFF_QH + row + d * 2)        = h1;
        *(__half*)(sm + OFF_QH + row + (d + 32) * 2) = h2;
        *(__half*)(sm + OFF_QL + row + d * 2)        = __float2half_rn(v1 - __half2float(h1));
        *(__half*)(sm + OFF_QL + row + (d + 32) * 2) = __float2half_rn(v2 - __half2float(h2));
    }
    // ---- load K (+RoPE) -> fp16 unsplit ----
    const float* kbase = g_qkv + (size_t)(bi * NTOK) * QKVN + DIM + h * DH;
#pragma unroll 4
    for (int it = 0; it < 32; it++) {
        int jj  = grp + 8 * it;
        int tok = (widx - 1) * WS + jj;
        float x1 = 0.f, x2 = 0.f;
        if (tok >= 0) {
            const float* p = kbase + (size_t)tok * QKVN;
            x1 = p[d]; x2 = p[d + 32];
        }
        float2 sc = g_rope[jj * 32 + d];
        uint32_t row = jj * QK_ROWB;
        *(__half*)(sm + OFF_K + row + d * 2)        = __float2half_rn(x1 * sc.y - x2 * sc.x);
        *(__half*)(sm + OFF_K + row + (d + 32) * 2) = __float2half_rn(x2 * sc.y + x1 * sc.x);
    }
    // ---- load V transposed -> fp16 unsplit ----
    const float* vbase = g_qkv + (size_t)(bi * NTOK) * QKVN + 2 * DIM + h * DH;
    for (int idx = tid; idx < 256 * 64; idx += 256) {
        int jj = idx >> 6, dd = idx & 63;
        int tok = (widx - 1) * WS + jj;
        float v = (tok < 0) ? 0.f : vbase[(size_t)tok * QKVN + dd];
        *(__half*)(sm + OFF_V + dd * PV_ROWB + jj * 2) = __float2half_rn(v);
    }
    __syncthreads();   // the ONLY barrier

    // ---- S = Q K^T, K-tiles [wid, wid+8] (valid column band) ----
    float acc[18][4];
#pragma unroll
    for (int nt = 0; nt < 18; nt++)
#pragma unroll
        for (int i = 0; i < 4; i++) acc[nt][i] = 0.f;

    const uint32_t lrq = (lane & 15) * QK_ROWB + (lane >> 4) * 16;
    const uint32_t lrp = (lane & 15) * PV_ROWB + (lane >> 4) * 16;

#pragma unroll
    for (int ks = 0; ks < 4; ks++) {
        const uint32_t ko = ks * 32;
        uint32_t qh[4], ql[4];
        ldm_x4(qh, sb + OFF_QH + wid * 16 * QK_ROWB + ko + lrq);
        ldm_x4(ql, sb + OFF_QL + wid * 16 * QK_ROWB + ko + lrq);
#pragma unroll
        for (int t = 0; t < 9; t++) {
            uint32_t rk[4];
            ldm_x4(rk, sb + OFF_K + (wid + t) * 16 * QK_ROWB + ko + lrq);
            uint32_t b0[2] = {rk[0], rk[2]}, b1[2] = {rk[1], rk[3]};
            mma16816h(acc[2 * t],     qh, b0);
            mma16816h(acc[2 * t],     ql, b0);
            mma16816h(acc[2 * t + 1], qh, b1);
            mma16816h(acc[2 * t + 1], ql, b1);
        }
    }

    // ---- mask + softmax (exp only; normalization deferred) ----
    const int q4 = lane & 3;
    const int cbase = 16 * wid;
    float inv[2];
#pragma unroll
    for (int i01 = 0; i01 < 2; i01++) {
        int r = wid * 16 + (lane >> 2) + i01 * 8;
        float mx = -1e30f;
#pragma unroll
        for (int nt = 0; nt < 18; nt++)
#pragma unroll
            for (int e = 0; e < 2; e++) {
                int c = cbase + 8 * nt + 2 * q4 + e;
                bool keep = (c >= r) && (c <= r + WS) && (widx > 0 || c >= WS);
                float& v = acc[nt][i01 * 2 + e];
                if (!keep) v = -1e30f;
                mx = fmaxf(mx, v);
            }
        mx = fmaxf(mx, __shfl_xor_sync(0xffffffffu, mx, 1));
        mx = fmaxf(mx, __shfl_xor_sync(0xffffffffu, mx, 2));
        float sum = 0.f;
#pragma unroll
        for (int nt = 0; nt < 18; nt++)
#pragma unroll
            for (int e = 0; e < 2; e++) {
                float& v = acc[nt][i01 * 2 + e];
                v = __expf(v - mx);
                sum += v;
            }
        sum += __shfl_xor_sync(0xffffffffu, sum, 1);
        sum += __shfl_xor_sync(0xffffffffu, sum, 2);
        inv[i01] = 1.0f / sum;
    }

    // ---- O = P V, P fp16 fragments straight from acc registers ----
    float o[8][4];
#pragma unroll
    for (int nt = 0; nt < 8; nt++)
#pragma unroll
        for (int i = 0; i < 4; i++) o[nt][i] = 0.f;

#pragma unroll
    for (int t = 0; t < 9; t++) {
        uint32_t ph[4];
#pragma unroll
        for (int rr = 0; rr < 2; rr++) {
            const float* f = acc[2 * t + rr];
            ph[2 * rr]     = pack_half2(f[0], f[1]);
            ph[2 * rr + 1] = pack_half2(f[2], f[3]);
        }
        const uint32_t ko = (wid + t) * 32;
#pragma unroll
        for (int nt2 = 0; nt2 < 4; nt2++) {
            uint32_t rv[4];
            ldm_x4(rv, sb + OFF_V + nt2 * 16 * PV_ROWB + ko + lrp);
            uint32_t v0[2] = {rv[0], rv[2]}, v1[2] = {rv[1], rv[3]};
            mma16816h(o[2 * nt2],     ph, v0);
            mma16816h(o[2 * nt2 + 1], ph, v1);
        }
    }

    // ---- epilogue: normalize rows, write fp16 hi/lo (feeds GEMM2) ----
    const int gr = lane >> 2;
#pragma unroll
    for (int i01 = 0; i01 < 2; i01++) {
        int row = widx * WS + wid * 16 + gr + i01 * 8;
        size_t base = (size_t)(bi * NTOK + row) * DIM + h * DH;
        float nrm = inv[i01];
#pragma unroll
        for (int nt = 0; nt < 8; nt++) {
            int col = nt * 8 + 2 * q4;
            float v0 = o[nt][i01 * 2] * nrm, v1 = o[nt][i01 * 2 + 1] * nrm;
            __half2 hv = __floats2half2_rn(v0, v1);
            __half2 lv = __floats2half2_rn(v0 - __half2float(__low2half(hv)),
                                           v1 - __half2float(__high2half(hv)));
            *(__half2*)&g_ah[base + col] = hv;
            *(__half2*)&g_al[base + col] = lv;
        }
    }
}

// ---------------------------------------------------------------------------
extern "C" void kernel_launch(void* const* d_in, const int* in_sizes, int n_in,
                              void* d_out, int out_size)
{
    const float* x    = (const float*)d_in[0];
    const float* Wqkv = (const float*)d_in[1];
    const float* Wout = (const float*)d_in[2];
    float* out = (float*)d_out;

    float *qkv_p;
    __half *xh, *xl, *wq, *wo, *ah, *al;
    cudaGetSymbolAddress((void**)&qkv_p, g_qkv);
    cudaGetSymbolAddress((void**)&xh, g_xh); cudaGetSymbolAddress((void**)&xl, g_xl);
    cudaGetSymbolAddress((void**)&wq, g_wq); cudaGetSymbolAddress((void**)&wo, g_wo);
    cudaGetSymbolAddress((void**)&ah, g_ah); cudaGetSymbolAddress((void**)&al, g_al);

    cudaFuncSetAttribute(gemm_fp16x2,
                         cudaFuncAttributeMaxDynamicSharedMemorySize, GSMEM_BYTES);
    cudaFuncSetAttribute(attn_mma_kernel,
                         cudaFuncAttributeMaxDynamicSharedMemorySize, ASMEM_BYTES);

    rope_table_kernel<<<32, 256>>>();
    split_f32h<<<(MTOT * DIM / 4 + 255) / 256, 256>>>(x, xh, xl, MTOT * DIM / 4);
    transpose_h<<<dim3(QKVN / 32, DIM / 32), 256>>>(Wqkv, wq, DIM, QKVN);
    transpose_h<<<dim3(DIM / 32, DIM / 32), 256>>>(Wout, wo, DIM, DIM);

    // 1) qkv = x @ Wqkv   (fp16x2)
    gemm_fp16x2<<<dim3(QKVN / 128, MTOT / 128), 128, GSMEM_BYTES>>>(
        xh, xl, wq, qkv_p, MTOT, QKVN, DIM);

    // 2) local attention (fp16, halved MMA count)
    attn_mma_kernel<<<dim3(NWIN, NHEAD, BATCH), 256, ASMEM_BYTES>>>();

    // 3) out = attn @ Wout (fp16x2)
    gemm_fp16x2<<<dim3(DIM / 128, MTOT / 128), 128, GSMEM_BYTES>>>(
        ah, al, wo, out, MTOT, DIM, DIM);
}